// round 7
// baseline (speedup 1.0000x reference)
#include <cuda_runtime.h>
#include <cuda_bf16.h>
#include <cstdint>

#define BB 8
#define NN 256
#define DD 64
#define ES 72   // E smem row stride (floats), conflict-free fragment LDS

__device__ float g_node_x[BB * NN * DD];   // emb_node @ Wn + bn
__device__ float g_sx_relu[BB * NN * DD];  // relu(emb_node @ Wsn + bsn)
__device__ float4 g_Wpack[1024];           // We fragments, tf32-rounded, b-frag order

// ---------------------------------------------------------------------------
// helpers
// ---------------------------------------------------------------------------
__device__ __forceinline__ float cvt_tf32(float x) {
    float r;
    asm("cvt.rna.tf32.f32 %0, %1;" : "=f"(r) : "f"(x));
    return r;
}
__device__ __forceinline__ uint32_t fbits(float x) { return __float_as_uint(x); }

__device__ __forceinline__ void mma_tf32(float* c, const uint32_t* a,
                                         uint32_t b0, uint32_t b1) {
    asm volatile(
        "mma.sync.aligned.m16n8k8.row.col.f32.tf32.tf32.f32 "
        "{%0,%1,%2,%3}, {%4,%5,%6,%7}, {%8,%9}, {%0,%1,%2,%3};"
        : "+f"(c[0]), "+f"(c[1]), "+f"(c[2]), "+f"(c[3])
        : "r"(a[0]), "r"(a[1]), "r"(a[2]), "r"(a[3]), "r"(b0), "r"(b1));
}

__device__ __forceinline__ void cp_async16(uint32_t saddr, const void* gptr) {
    asm volatile("cp.async.cg.shared.global [%0], [%1], 16;"
                 :: "r"(saddr), "l"(gptr));
}

// ---------------------------------------------------------------------------
// Kernel A: node GEMMs (4 rows / 256-thread block) + W fragment packing.
// ---------------------------------------------------------------------------
__global__ __launch_bounds__(256)
void node_gemm_kernel(const float* __restrict__ emb_node,
                      const float* __restrict__ Wn,
                      const float* __restrict__ bn,
                      const float* __restrict__ Wsn,
                      const float* __restrict__ bsn,
                      const float* __restrict__ We) {
    if (blockIdx.x == 0) {
#pragma unroll
        for (int it = 0; it < 4; it++) {
            const int e = threadIdx.x + it * 256;   // 0..1023
            const int p = e >> 8;
            const int nt = (e >> 5) & 7;
            const int l = e & 31;
            const int n = nt * 8 + (l >> 2);
            const int k0 = p * 16 + (l & 3);
            g_Wpack[e] = make_float4(cvt_tf32(We[k0 * DD + n]),
                                     cvt_tf32(We[(k0 + 4) * DD + n]),
                                     cvt_tf32(We[(k0 + 8) * DD + n]),
                                     cvt_tf32(We[(k0 + 12) * DD + n]));
        }
    }
    const int sub = threadIdx.x >> 6;
    const int c = threadIdx.x & 63;
    const int r = blockIdx.x * 4 + sub;
    __shared__ float e[4][DD];
    e[sub][c] = emb_node[r * DD + c];
    __syncthreads();
    float a1 = bn[c];
    float a2 = bsn[c];
#pragma unroll
    for (int k = 0; k < DD; k++) {
        const float ev = e[sub][k];
        a1 = fmaf(ev, Wn[k * DD + c], a1);
        a2 = fmaf(ev, Wsn[k * DD + c], a2);
    }
    g_node_x[r * DD + c] = a1;
    g_sx_relu[r * DD + c] = fmaxf(a2, 0.0f);
}

// ---------------------------------------------------------------------------
// Kernel B: per (b,i). edge_x[256x64] = E @ We via tf32 mma.sync.
// 512 threads, 16 warps; warp w owns j-rows [w*16, w*16+16):
//  - per-warp cp.async for its own 16 rows (no block barrier)
//  - W b-frags via LDG.128 from g_Wpack (L1-resident)
//  - acc tile 1 m-tile x 8 n-tiles (32 regs) -> ~60 regs -> 2 CTAs x 512 = 47% occ
// ---------------------------------------------------------------------------
__global__ __launch_bounds__(512, 2)
void edge_mma_kernel(const float* __restrict__ A,
                     const float* __restrict__ emb_edge,
                     const float* __restrict__ be,
                     float* __restrict__ out) {
    const int i = blockIdx.x;
    const int b = blockIdx.y;
    const int tid = threadIdx.x;
    const int lane = tid & 31;
    const int warp = tid >> 5;       // 0..15
    const int g = lane >> 2;         // 0..7
    const int t = lane & 3;          // 0..3
    const int jb = warp * 16;
    const int bi = b * NN + i;

    extern __shared__ float sh[];
    float* Esh = sh;               // 256*72 floats (E, then reused as epi tile)
    float* Ash = sh + NN * ES;     // 256
    float* red = Ash + NN;         // 16*64

    // ---- per-warp E staging via cp.async (16 rows = 8 iters) ----
    {
        const float* Eg = emb_edge + (size_t)bi * NN * DD;
        const uint32_t esh_u32 = (uint32_t)__cvta_generic_to_shared(Esh);
#pragma unroll
        for (int it = 0; it < 8; it++) {
            const int row = jb + it * 2 + (lane >> 4);
            const int c16 = lane & 15;
            cp_async16(esh_u32 + (uint32_t)(row * ES + c16 * 4) * 4u,
                       Eg + row * DD + c16 * 4);
        }
        asm volatile("cp.async.commit_group;");
    }
    if (lane < 16) Ash[jb + lane] = A[(size_t)bi * NN + jb + lane];

    // ---- accumulators init with bias (while loads are in flight) ----
    float acc[8][4];
#pragma unroll
    for (int nt = 0; nt < 8; nt++) {
        const float b0 = __ldg(&be[nt * 8 + 2 * t]);
        const float b1 = __ldg(&be[nt * 8 + 2 * t + 1]);
        acc[nt][0] = b0; acc[nt][1] = b1;
        acc[nt][2] = b0; acc[nt][3] = b1;
    }

    asm volatile("cp.async.wait_group 0;");
    __syncwarp();

    // ---- main loop: 4 k-step pairs ----
#pragma unroll
    for (int p = 0; p < 4; p++) {
        uint32_t a[2][4];   // [kb-in-pair][reg]
#pragma unroll
        for (int kb2 = 0; kb2 < 2; kb2++) {
            const float* base = &Esh[(jb + g) * ES + p * 16 + kb2 * 8 + t];
            a[kb2][0] = fbits(cvt_tf32(base[0]));
            a[kb2][1] = fbits(cvt_tf32(base[8 * ES]));
            a[kb2][2] = fbits(cvt_tf32(base[4]));
            a[kb2][3] = fbits(cvt_tf32(base[8 * ES + 4]));
        }
        const float4* wrow = &g_Wpack[p * 256 + lane];
#pragma unroll
        for (int nt = 0; nt < 8; nt++) {
            const float4 w = __ldg(&wrow[nt * 32]);
            mma_tf32(acc[nt], a[0], fbits(w.x), fbits(w.y));
            mma_tf32(acc[nt], a[1], fbits(w.z), fbits(w.w));
        }
    }

    // ---- epilogue stage 1: scatter raw acc into THIS WARP's 16 rows ----
#pragma unroll
    for (int rh = 0; rh < 2; rh++) {
        const int row = jb + rh * 8 + g;
#pragma unroll
        for (int nt = 0; nt < 8; nt++) {
            *(float2*)&Esh[row * ES + nt * 8 + 2 * t] =
                make_float2(acc[nt][rh * 2], acc[nt][rh * 2 + 1]);
        }
    }
    __syncwarp();

    // ---- epilogue stage 2: coalesced read-back, relu->edge_out, aggregation ----
    const float* nx = g_node_x + (size_t)b * NN * DD;
    float* eo = out + BB * NN * DD + (size_t)bi * NN * DD;
    const int lr = lane >> 4;
    const int lc = (lane & 15) * 4;

    float p0 = 0.0f, p1 = 0.0f, p2 = 0.0f, p3 = 0.0f;
#pragma unroll
    for (int q = 0; q < 8; q++) {
        const int row = jb + 2 * q + lr;
        const float4 v = *(const float4*)&Esh[row * ES + lc];
        const float av = Ash[row];
        const float4 nv = *(const float4*)&nx[row * DD + lc];
        *(float4*)&eo[row * DD + lc] =
            make_float4(fmaxf(v.x, 0.0f), fmaxf(v.y, 0.0f),
                        fmaxf(v.z, 0.0f), fmaxf(v.w, 0.0f));
        p0 = fmaf(av * v.x, nv.x, p0);
        p1 = fmaf(av * v.y, nv.y, p1);
        p2 = fmaf(av * v.z, nv.z, p2);
        p3 = fmaf(av * v.w, nv.w, p3);
    }
    p0 += __shfl_xor_sync(0xffffffffu, p0, 16);
    p1 += __shfl_xor_sync(0xffffffffu, p1, 16);
    p2 += __shfl_xor_sync(0xffffffffu, p2, 16);
    p3 += __shfl_xor_sync(0xffffffffu, p3, 16);
    if (lane < 16)
        *(float4*)&red[warp * DD + lc] = make_float4(p0, p1, p2, p3);
    __syncthreads();

    if (tid < DD) {
        float s = 0.0f;
#pragma unroll
        for (int w = 0; w < 16; w++) s += red[w * DD + tid];
        out[(size_t)bi * DD + tid] = fmaxf(s, 0.0f) + g_sx_relu[(size_t)bi * DD + tid];
    }
}

// ---------------------------------------------------------------------------
// Launch
// ---------------------------------------------------------------------------
extern "C" void kernel_launch(void* const* d_in, const int* in_sizes, int n_in,
                              void* d_out, int out_size) {
    const float* A        = (const float*)d_in[0];
    const float* emb_node = (const float*)d_in[1];
    const float* emb_edge = (const float*)d_in[2];
    const float* Wn       = (const float*)d_in[3];
    const float* bn       = (const float*)d_in[4];
    const float* Wsn      = (const float*)d_in[5];
    const float* bsn      = (const float*)d_in[6];
    const float* We       = (const float*)d_in[7];
    const float* be       = (const float*)d_in[8];
    float* out = (float*)d_out;

    const int smem = (NN * ES + NN + 16 * DD) * sizeof(float); // 78848 B
    cudaFuncSetAttribute(edge_mma_kernel, cudaFuncAttributeMaxDynamicSharedMemorySize, smem);

    node_gemm_kernel<<<BB * NN / 4, 256>>>(emb_node, Wn, bn, Wsn, bsn, We);

    dim3 grid(NN, BB);
    edge_mma_kernel<<<grid, 512, smem>>>(A, emb_edge, be, out);
}

// round 10
// speedup vs baseline: 1.1017x; 1.1017x over previous
#include <cuda_runtime.h>
#include <cuda_bf16.h>
#include <cstdint>

#define BB 8
#define NN 256
#define DD 64
#define ES 72   // E smem row stride (floats), conflict-free fragment LDS

__device__ float g_node_x[BB * NN * DD];   // emb_node @ Wn + bn
__device__ float g_sx_relu[BB * NN * DD];  // relu(emb_node @ Wsn + bsn)
__device__ float4 g_Wpack[1024];           // We fragments, tf32-rounded, b-frag order

// ---------------------------------------------------------------------------
// helpers
// ---------------------------------------------------------------------------
__device__ __forceinline__ float cvt_tf32(float x) {
    float r;
    asm("cvt.rna.tf32.f32 %0, %1;" : "=f"(r) : "f"(x));
    return r;
}
__device__ __forceinline__ uint32_t fbits(float x) { return __float_as_uint(x); }

__device__ __forceinline__ void mma_tf32(float* c, const uint32_t* a,
                                         uint32_t b0, uint32_t b1) {
    asm volatile(
        "mma.sync.aligned.m16n8k8.row.col.f32.tf32.tf32.f32 "
        "{%0,%1,%2,%3}, {%4,%5,%6,%7}, {%8,%9}, {%0,%1,%2,%3};"
        : "+f"(c[0]), "+f"(c[1]), "+f"(c[2]), "+f"(c[3])
        : "r"(a[0]), "r"(a[1]), "r"(a[2]), "r"(a[3]), "r"(b0), "r"(b1));
}

__device__ __forceinline__ void cp_async16(uint32_t saddr, const void* gptr) {
    asm volatile("cp.async.cg.shared.global [%0], [%1], 16;"
                 :: "r"(saddr), "l"(gptr));
}

// ---------------------------------------------------------------------------
// Kernel A: node GEMMs (4 rows / 256-thread block) + W fragment packing.
// ---------------------------------------------------------------------------
__global__ __launch_bounds__(256)
void node_gemm_kernel(const float* __restrict__ emb_node,
                      const float* __restrict__ Wn,
                      const float* __restrict__ bn,
                      const float* __restrict__ Wsn,
                      const float* __restrict__ bsn,
                      const float* __restrict__ We) {
    if (blockIdx.x == 0) {
#pragma unroll
        for (int it = 0; it < 4; it++) {
            const int e = threadIdx.x + it * 256;   // 0..1023
            const int p = e >> 8;
            const int nt = (e >> 5) & 7;
            const int l = e & 31;
            const int n = nt * 8 + (l >> 2);
            const int k0 = p * 16 + (l & 3);
            g_Wpack[e] = make_float4(cvt_tf32(We[k0 * DD + n]),
                                     cvt_tf32(We[(k0 + 4) * DD + n]),
                                     cvt_tf32(We[(k0 + 8) * DD + n]),
                                     cvt_tf32(We[(k0 + 12) * DD + n]));
        }
    }
    const int sub = threadIdx.x >> 6;
    const int c = threadIdx.x & 63;
    const int r = blockIdx.x * 4 + sub;
    __shared__ float e[4][DD];
    e[sub][c] = emb_node[r * DD + c];
    __syncthreads();
    float a1 = bn[c];
    float a2 = bsn[c];
#pragma unroll
    for (int k = 0; k < DD; k++) {
        const float ev = e[sub][k];
        a1 = fmaf(ev, Wn[k * DD + c], a1);
        a2 = fmaf(ev, Wsn[k * DD + c], a2);
    }
    g_node_x[r * DD + c] = a1;
    g_sx_relu[r * DD + c] = fmaxf(a2, 0.0f);
}

// ---------------------------------------------------------------------------
// Kernel B: per (b,i). edge_x[256x64] = E @ We via tf32 mma.sync.
// 8 warps; warp w fully owns j-rows [w*32, w*32+32):
//  - cp.async split into 4 commit groups by 16-k slab; waits interleaved with
//    the p-loop so MMA starts after the first 2KB lands (latency overlap)
//  - W b-frags via LDG.128 from g_Wpack (L1-resident)
//  - warp-local coalesced epilogue through the dead E smem tile.
// ---------------------------------------------------------------------------
__global__ __launch_bounds__(256, 2)
void edge_mma_kernel(const float* __restrict__ A,
                     const float* __restrict__ emb_edge,
                     const float* __restrict__ be,
                     float* __restrict__ out) {
    const int i = blockIdx.x;
    const int b = blockIdx.y;
    const int tid = threadIdx.x;
    const int lane = tid & 31;
    const int warp = tid >> 5;
    const int g = lane >> 2;     // 0..7
    const int t = lane & 3;      // 0..3
    const int jb = warp * 32;
    const int bi = b * NN + i;

    extern __shared__ float sh[];
    float* Esh = sh;               // 256*72 floats (E, then reused as epi tile)
    float* Ash = sh + NN * ES;     // 256
    float* red = Ash + NN;         // 8*64

    // ---- per-warp E staging: 4 commit groups, one per 16-k slab ----
    {
        const float* Eg = emb_edge + (size_t)bi * NN * DD;
        const uint32_t esh_u32 = (uint32_t)__cvta_generic_to_shared(Esh);
        const int lrow = lane >> 2;        // 0..7
        const int lc = lane & 3;           // chunk-in-group
#pragma unroll
        for (int kg = 0; kg < 4; kg++) {
#pragma unroll
            for (int it = 0; it < 4; it++) {
                const int row = jb + it * 8 + lrow;
                const int c16 = kg * 4 + lc;
                cp_async16(esh_u32 + (uint32_t)(row * ES + c16 * 4) * 4u,
                           Eg + row * DD + c16 * 4);
            }
            asm volatile("cp.async.commit_group;");
        }
    }
    Ash[jb + lane] = A[(size_t)bi * NN + jb + lane];

    // ---- accumulators init with bias (while loads are in flight) ----
    float acc[2][8][4];
#pragma unroll
    for (int nt = 0; nt < 8; nt++) {
        const float b0 = __ldg(&be[nt * 8 + 2 * t]);
        const float b1 = __ldg(&be[nt * 8 + 2 * t + 1]);
#pragma unroll
        for (int mt = 0; mt < 2; mt++) {
            acc[mt][nt][0] = b0; acc[mt][nt][1] = b1;
            acc[mt][nt][2] = b0; acc[mt][nt][3] = b1;
        }
    }

    // ---- main loop: 4 k-step pairs, incremental cp.async waits ----
#pragma unroll
    for (int p = 0; p < 4; p++) {
        if (p == 0)      asm volatile("cp.async.wait_group 3;");
        else if (p == 1) asm volatile("cp.async.wait_group 2;");
        else if (p == 2) asm volatile("cp.async.wait_group 1;");
        else             asm volatile("cp.async.wait_group 0;");
        __syncwarp();

        uint32_t a[2][2][4];   // [kb-in-pair][mt][reg]
#pragma unroll
        for (int kb2 = 0; kb2 < 2; kb2++) {
#pragma unroll
            for (int mt = 0; mt < 2; mt++) {
                const float* base = &Esh[(jb + mt * 16 + g) * ES + p * 16 + kb2 * 8 + t];
                a[kb2][mt][0] = fbits(cvt_tf32(base[0]));
                a[kb2][mt][1] = fbits(cvt_tf32(base[8 * ES]));
                a[kb2][mt][2] = fbits(cvt_tf32(base[4]));
                a[kb2][mt][3] = fbits(cvt_tf32(base[8 * ES + 4]));
            }
        }
        const float4* wrow = &g_Wpack[p * 256 + lane];
#pragma unroll
        for (int nt = 0; nt < 8; nt++) {
            const float4 w = __ldg(&wrow[nt * 32]);
            const uint32_t b0 = fbits(w.x), b1 = fbits(w.y);
            const uint32_t b2 = fbits(w.z), b3 = fbits(w.w);
            mma_tf32(acc[0][nt], a[0][0], b0, b1);
            mma_tf32(acc[1][nt], a[0][1], b0, b1);
            mma_tf32(acc[0][nt], a[1][0], b2, b3);
            mma_tf32(acc[1][nt], a[1][1], b2, b3);
        }
    }

    // ---- epilogue stage 1: scatter raw acc into THIS WARP's rows of Esh ----
#pragma unroll
    for (int mt = 0; mt < 2; mt++) {
#pragma unroll
        for (int rh = 0; rh < 2; rh++) {
            const int row = jb + mt * 16 + rh * 8 + g;
#pragma unroll
            for (int nt = 0; nt < 8; nt++) {
                *(float2*)&Esh[row * ES + nt * 8 + 2 * t] =
                    make_float2(acc[mt][nt][rh * 2], acc[mt][nt][rh * 2 + 1]);
            }
        }
    }
    __syncwarp();

    // ---- epilogue stage 2: coalesced read-back, relu->edge_out, aggregation ----
    const float* nx = g_node_x + (size_t)b * NN * DD;
    float* eo = out + BB * NN * DD + (size_t)bi * NN * DD;
    const int lr = lane >> 4;
    const int lc = (lane & 15) * 4;

    float p0 = 0.0f, p1 = 0.0f, p2 = 0.0f, p3 = 0.0f;
#pragma unroll
    for (int q = 0; q < 16; q++) {
        const int row = jb + 2 * q + lr;
        const float4 v = *(const float4*)&Esh[row * ES + lc];
        const float av = Ash[row];
        const float4 nv = *(const float4*)&nx[row * DD + lc];
        *(float4*)&eo[row * DD + lc] =
            make_float4(fmaxf(v.x, 0.0f), fmaxf(v.y, 0.0f),
                        fmaxf(v.z, 0.0f), fmaxf(v.w, 0.0f));
        p0 = fmaf(av * v.x, nv.x, p0);
        p1 = fmaf(av * v.y, nv.y, p1);
        p2 = fmaf(av * v.z, nv.z, p2);
        p3 = fmaf(av * v.w, nv.w, p3);
    }
    p0 += __shfl_xor_sync(0xffffffffu, p0, 16);
    p1 += __shfl_xor_sync(0xffffffffu, p1, 16);
    p2 += __shfl_xor_sync(0xffffffffu, p2, 16);
    p3 += __shfl_xor_sync(0xffffffffu, p3, 16);
    if (lane < 16)
        *(float4*)&red[warp * DD + lc] = make_float4(p0, p1, p2, p3);
    __syncthreads();

    if (tid < DD) {
        float s = 0.0f;
#pragma unroll
        for (int w = 0; w < 8; w++) s += red[w * DD + tid];
        out[(size_t)bi * DD + tid] = fmaxf(s, 0.0f) + g_sx_relu[(size_t)bi * DD + tid];
    }
}

// ---------------------------------------------------------------------------
// Launch
// ---------------------------------------------------------------------------
extern "C" void kernel_launch(void* const* d_in, const int* in_sizes, int n_in,
                              void* d_out, int out_size) {
    const float* A        = (const float*)d_in[0];
    const float* emb_node = (const float*)d_in[1];
    const float* emb_edge = (const float*)d_in[2];
    const float* Wn       = (const float*)d_in[3];
    const float* bn       = (const float*)d_in[4];
    const float* Wsn      = (const float*)d_in[5];
    const float* bsn      = (const float*)d_in[6];
    const float* We       = (const float*)d_in[7];
    const float* be       = (const float*)d_in[8];
    float* out = (float*)d_out;

    const int smem = (NN * ES + NN + 8 * DD) * sizeof(float); // 76800 B
    cudaFuncSetAttribute(edge_mma_kernel, cudaFuncAttributeMaxDynamicSharedMemorySize, smem);

    node_gemm_kernel<<<BB * NN / 4, 256>>>(emb_node, Wn, bn, Wsn, bsn, We);

    dim3 grid(NN, BB);
    edge_mma_kernel<<<grid, 256, smem>>>(A, emb_edge, be, out);
}